// round 1
// baseline (speedup 1.0000x reference)
#include <cuda_runtime.h>
#include <cuda_bf16.h>
#include <math.h>

// ---------------------------------------------------------------------------
// Problem constants
//   B=4, L=4096, D_MODEL=1024, H=2, DEPTH=512, M_FEAT=256
//   scale = 512^{-1/4};  scale^2 = 1/sqrt(512);  ratio = 1/16
// ---------------------------------------------------------------------------
#define BATCH     4
#define SEQ       4096
#define DMODEL    1024
#define HEADS     2
#define DEPTH     512
#define MFEAT     256
#define ROWS      (BATCH*SEQ)          // 16384
#define ROWS2     (ROWS*HEADS)         // 32768 (rows of the [*,512] view)

#define SCALE2    0.044194173824159216f   // 1/sqrt(512)
#define FSCALE    0.21022410381342864f    // 512^{-0.25}
#define RATIO     0.0625f                 // 1/sqrt(256)
#define EPS       1e-6f

// ---------------------------------------------------------------------------
// Scratch (device globals; allocation is banned)
// ---------------------------------------------------------------------------
__device__ float g_Q [ (size_t)ROWS * DMODEL ];   // 64 MB
__device__ float g_K [ (size_t)ROWS * DMODEL ];
__device__ float g_V [ (size_t)ROWS * DMODEL ];
__device__ float g_dQ[ (size_t)ROWS2 * MFEAT ];   // 32 MB (dash_q -> q')
__device__ float g_dK[ (size_t)ROWS2 * MFEAT ];   // 32 MB (dash_k -> k')
__device__ float g_diagK[ ROWS2 ];
__device__ float g_rmaxK[ ROWS2 ];
__device__ float g_kmax [ BATCH*HEADS ];
__device__ float g_C [ (size_t)ROWS * DMODEL ];   // concat buffer

// ---------------------------------------------------------------------------
// SGEMM: C = alpha * A(MxK) * op(B) (+ bias), 128x128 tile, 8x8/thread.
// bTrans==0 : B is [K,N] row-major.
// bTrans==1 : B is [N,K] row-major (computes A @ B^T).
// M % 128 == 0, N % 128 == 0, K % 16 == 0 (all true for our shapes).
// ---------------------------------------------------------------------------
__global__ __launch_bounds__(256)
void sgemm_kernel(const float* __restrict__ A, const float* __restrict__ B,
                  const float* __restrict__ bias, float* __restrict__ C,
                  int M, int N, int K, float alpha, int bTrans)
{
    __shared__ float As[16][128];
    __shared__ float Bs[16][128];

    const int tid = threadIdx.x;
    const int bm  = blockIdx.y * 128;
    const int bn  = blockIdx.x * 128;
    const int tx  = tid & 15;
    const int ty  = tid >> 4;

    float acc[8][8];
    #pragma unroll
    for (int i = 0; i < 8; i++)
        #pragma unroll
        for (int j = 0; j < 8; j++) acc[i][j] = 0.f;

    for (int k0 = 0; k0 < K; k0 += 16) {
        // ---- load A tile (128 rows x 16 k), transposed into As[k][m]
        #pragma unroll
        for (int c = 0; c < 2; c++) {
            int chunk = tid + 256 * c;          // 0..511
            int row   = chunk >> 2;             // 0..127
            int col   = (chunk & 3) * 4;        // 0,4,8,12
            float4 v = *reinterpret_cast<const float4*>(
                &A[(size_t)(bm + row) * K + k0 + col]);
            As[col+0][row] = v.x; As[col+1][row] = v.y;
            As[col+2][row] = v.z; As[col+3][row] = v.w;
        }
        // ---- load B tile into Bs[k][n]
        if (!bTrans) {
            #pragma unroll
            for (int c = 0; c < 2; c++) {
                int chunk = tid + 256 * c;
                int kk    = chunk >> 5;           // 0..15
                int col   = (chunk & 31) * 4;     // 0..124
                float4 v = *reinterpret_cast<const float4*>(
                    &B[(size_t)(k0 + kk) * N + bn + col]);
                *reinterpret_cast<float4*>(&Bs[kk][col]) = v;
            }
        } else {
            #pragma unroll
            for (int c = 0; c < 2; c++) {
                int chunk = tid + 256 * c;
                int n     = chunk >> 2;           // 0..127
                int kk4   = (chunk & 3) * 4;
                float4 v = *reinterpret_cast<const float4*>(
                    &B[(size_t)(bn + n) * K + k0 + kk4]);
                Bs[kk4+0][n] = v.x; Bs[kk4+1][n] = v.y;
                Bs[kk4+2][n] = v.z; Bs[kk4+3][n] = v.w;
            }
        }
        __syncthreads();

        #pragma unroll
        for (int kk = 0; kk < 16; kk++) {
            float a[8], b[8];
            #pragma unroll
            for (int i = 0; i < 8; i += 4) {
                float4 va = *reinterpret_cast<const float4*>(&As[kk][ty*8 + i]);
                a[i+0]=va.x; a[i+1]=va.y; a[i+2]=va.z; a[i+3]=va.w;
            }
            #pragma unroll
            for (int j = 0; j < 8; j += 4) {
                float4 vb = *reinterpret_cast<const float4*>(&Bs[kk][tx*8 + j]);
                b[j+0]=vb.x; b[j+1]=vb.y; b[j+2]=vb.z; b[j+3]=vb.w;
            }
            #pragma unroll
            for (int i = 0; i < 8; i++)
                #pragma unroll
                for (int j = 0; j < 8; j++)
                    acc[i][j] += a[i] * b[j];
        }
        __syncthreads();
    }

    // ---- epilogue
    #pragma unroll
    for (int i = 0; i < 8; i++) {
        int row = bm + ty*8 + i;
        #pragma unroll
        for (int j = 0; j < 8; j += 4) {
            int col = bn + tx*8 + j;
            float4 o;
            o.x = alpha*acc[i][j+0]; o.y = alpha*acc[i][j+1];
            o.z = alpha*acc[i][j+2]; o.w = alpha*acc[i][j+3];
            if (bias) {
                o.x += bias[col+0]; o.y += bias[col+1];
                o.z += bias[col+2]; o.w += bias[col+3];
            }
            *reinterpret_cast<float4*>(&C[(size_t)row * N + col]) = o;
        }
    }
}

// ---------------------------------------------------------------------------
// q' : per row r (of 32768) compute diag from Y row, row-max of dash row,
//      then dash <- ratio*(exp(dash - diag - rmax) + eps)   (in place)
// one warp per row
// ---------------------------------------------------------------------------
__global__ __launch_bounds__(256)
void qprime_kernel(const float* __restrict__ Y, float* __restrict__ dash)
{
    int warp = (blockIdx.x * blockDim.x + threadIdx.x) >> 5;
    int lane = threadIdx.x & 31;
    if (warp >= ROWS2) return;

    const float* y = Y + (size_t)warp * DEPTH;
    float ss = 0.f;
    #pragma unroll
    for (int i = 0; i < DEPTH/32; i++) { float v = y[lane + 32*i]; ss += v*v; }
    #pragma unroll
    for (int off = 16; off; off >>= 1) ss += __shfl_xor_sync(0xffffffff, ss, off);
    float diag = 0.5f * SCALE2 * ss;

    float* dr = dash + (size_t)warp * MFEAT;
    float vals[MFEAT/32];
    float mx = -1e30f;
    #pragma unroll
    for (int i = 0; i < MFEAT/32; i++) { vals[i] = dr[lane + 32*i]; mx = fmaxf(mx, vals[i]); }
    #pragma unroll
    for (int off = 16; off; off >>= 1) mx = fmaxf(mx, __shfl_xor_sync(0xffffffff, mx, off));

    #pragma unroll
    for (int i = 0; i < MFEAT/32; i++)
        dr[lane + 32*i] = RATIO * (__expf(vals[i] - diag - mx) + EPS) * 0.f
                        + RATIO * (expf(vals[i] - diag - mx) + EPS);
}

// ---------------------------------------------------------------------------
// k path step 1: per-row diag + per-row max (one warp per row)
// ---------------------------------------------------------------------------
__global__ __launch_bounds__(256)
void kstat_kernel(const float* __restrict__ Y, const float* __restrict__ dash,
                  float* __restrict__ diagK, float* __restrict__ rmaxK)
{
    int warp = (blockIdx.x * blockDim.x + threadIdx.x) >> 5;
    int lane = threadIdx.x & 31;
    if (warp >= ROWS2) return;

    const float* y = Y + (size_t)warp * DEPTH;
    float ss = 0.f;
    #pragma unroll
    for (int i = 0; i < DEPTH/32; i++) { float v = y[lane + 32*i]; ss += v*v; }
    #pragma unroll
    for (int off = 16; off; off >>= 1) ss += __shfl_xor_sync(0xffffffff, ss, off);

    const float* dr = dash + (size_t)warp * MFEAT;
    float mx = -1e30f;
    #pragma unroll
    for (int i = 0; i < MFEAT/32; i++) mx = fmaxf(mx, dr[lane + 32*i]);
    #pragma unroll
    for (int off = 16; off; off >>= 1) mx = fmaxf(mx, __shfl_xor_sync(0xffffffff, mx, off));

    if (lane == 0) { diagK[warp] = 0.5f * SCALE2 * ss; rmaxK[warp] = mx; }
}

// k path step 2: reduce row maxima over the sequence per (b,h).
// row index: r = b*8192 + l*2 + h.  8 blocks, one per (b,h).
__global__ __launch_bounds__(256)
void kmax_kernel(const float* __restrict__ rmaxK, float* __restrict__ kmax)
{
    int bh = blockIdx.x;          // b*2+h
    int b  = bh >> 1, h = bh & 1;
    __shared__ float sm[256];
    float mx = -1e30f;
    for (int l = threadIdx.x; l < SEQ; l += 256)
        mx = fmaxf(mx, rmaxK[b*8192 + l*2 + h]);
    sm[threadIdx.x] = mx;
    __syncthreads();
    for (int s = 128; s; s >>= 1) {
        if (threadIdx.x < s) sm[threadIdx.x] = fmaxf(sm[threadIdx.x], sm[threadIdx.x + s]);
        __syncthreads();
    }
    if (threadIdx.x == 0) kmax[bh] = sm[0];
}

// k path step 3: dash_k <- ratio*(exp(dash - diag[r] - kmax[b,h]) + eps)
__global__ __launch_bounds__(256)
void kexp_kernel(float* __restrict__ dash, const float* __restrict__ diagK,
                 const float* __restrict__ kmax)
{
    size_t idx = (size_t)blockIdx.x * blockDim.x + threadIdx.x;
    size_t total = (size_t)ROWS2 * MFEAT;
    if (idx >= total) return;
    int r = (int)(idx >> 8);               // MFEAT = 256
    int b = r >> 13;                       // r / 8192
    int h = r & 1;
    float v = dash[idx];
    dash[idx] = RATIO * (expf(v - diagK[r] - kmax[b*2 + h]) + EPS);
}

// ---------------------------------------------------------------------------
// Attention mix: per (s,h) block.
//   S[bb,bp] = sum_m q'[bb]·k'[bp]    (4x4)
//   out[l=s,h,bb,d] = (sum_bp S[bb,bp] * V[bp,d]) / rowsum_bp(S[bb])
// written into the scrambled "concat" flat layout: idx = s*4096 + h*2048 + bb*512 + d
// ---------------------------------------------------------------------------
__global__ __launch_bounds__(256)
void attn_mix_kernel(const float* __restrict__ QP, const float* __restrict__ KP,
                     const float* __restrict__ V, float* __restrict__ C)
{
    int blk = blockIdx.x;               // s*2 + h
    int s = blk >> 1, h = blk & 1;
    __shared__ float q_s[4][MFEAT];
    __shared__ float k_s[4][MFEAT];
    __shared__ float S[4][4];
    __shared__ float rs[4];
    int tid = threadIdx.x;

    #pragma unroll
    for (int bb = 0; bb < 4; bb++) {
        size_t r = (size_t)((bb*SEQ + s)*HEADS + h);
        q_s[bb][tid] = QP[r*MFEAT + tid];
        k_s[bb][tid] = KP[r*MFEAT + tid];
    }
    __syncthreads();

    // 16 dot products, 16 lanes each
    int p = tid >> 4, lane16 = tid & 15;
    int bb = p >> 2, bp = p & 3;
    float acc = 0.f;
    #pragma unroll
    for (int m = 0; m < MFEAT; m += 16) acc += q_s[bb][m + lane16] * k_s[bp][m + lane16];
    #pragma unroll
    for (int off = 8; off; off >>= 1) acc += __shfl_down_sync(0xffffffff, acc, off, 16);
    if (lane16 == 0) S[bb][bp] = acc;
    __syncthreads();
    if (tid < 4) rs[tid] = S[tid][0] + S[tid][1] + S[tid][2] + S[tid][3];
    __syncthreads();

    float s00=S[0][0],s01=S[0][1],s02=S[0][2],s03=S[0][3];
    float s10=S[1][0],s11=S[1][1],s12=S[1][2],s13=S[1][3];
    float s20=S[2][0],s21=S[2][1],s22=S[2][2],s23=S[2][3];
    float s30=S[3][0],s31=S[3][1],s32=S[3][2],s33=S[3][3];
    float r0 = 1.f/rs[0], r1 = 1.f/rs[1], r2 = 1.f/rs[2], r3 = 1.f/rs[3];

    size_t cbase = (size_t)s*4096 + (size_t)h*2048;
    for (int d = tid; d < DEPTH; d += 256) {
        float v0 = V[(size_t)((0*SEQ + s)*HEADS + h)*DEPTH + d];
        float v1 = V[(size_t)((1*SEQ + s)*HEADS + h)*DEPTH + d];
        float v2 = V[(size_t)((2*SEQ + s)*HEADS + h)*DEPTH + d];
        float v3 = V[(size_t)((3*SEQ + s)*HEADS + h)*DEPTH + d];
        C[cbase + 0*512 + d] = (s00*v0 + s01*v1 + s02*v2 + s03*v3) * r0;
        C[cbase + 1*512 + d] = (s10*v0 + s11*v1 + s12*v2 + s13*v3) * r1;
        C[cbase + 2*512 + d] = (s20*v0 + s21*v1 + s22*v2 + s23*v3) * r2;
        C[cbase + 3*512 + d] = (s30*v0 + s31*v1 + s32*v2 + s33*v3) * r3;
    }
}

// ---------------------------------------------------------------------------
// Launch
// ---------------------------------------------------------------------------
extern "C" void kernel_launch(void* const* d_in, const int* in_sizes, int n_in,
                              void* d_out, int out_size)
{
    const float* query = (const float*)d_in[0];
    const float* key   = (const float*)d_in[1];
    const float* value = (const float*)d_in[2];
    // d_in[3] = mask (unused by the reference math)
    const float* Wq = (const float*)d_in[4];
    const float* bq = (const float*)d_in[5];
    const float* Wk = (const float*)d_in[6];
    const float* bk = (const float*)d_in[7];
    const float* Wv = (const float*)d_in[8];
    const float* bv = (const float*)d_in[9];
    const float* Wo = (const float*)d_in[10];
    const float* bo = (const float*)d_in[11];
    const float* feats = (const float*)d_in[12];   // [256, 512]
    float* out = (float*)d_out;

    float *Q, *K, *V, *dQ, *dK, *diagK, *rmaxK, *kmax, *C;
    cudaGetSymbolAddress((void**)&Q,     g_Q);
    cudaGetSymbolAddress((void**)&K,     g_K);
    cudaGetSymbolAddress((void**)&V,     g_V);
    cudaGetSymbolAddress((void**)&dQ,    g_dQ);
    cudaGetSymbolAddress((void**)&dK,    g_dK);
    cudaGetSymbolAddress((void**)&diagK, g_diagK);
    cudaGetSymbolAddress((void**)&rmaxK, g_rmaxK);
    cudaGetSymbolAddress((void**)&kmax,  g_kmax);
    cudaGetSymbolAddress((void**)&C,     g_C);

    // 1-3: projections  Y = X @ W + b     (16384 x 1024 x 1024)
    dim3 gProj(DMODEL/128, ROWS/128);
    sgemm_kernel<<<gProj, 256>>>(query, Wq, bq, Q, ROWS, DMODEL, DMODEL, 1.f, 0);
    sgemm_kernel<<<gProj, 256>>>(key,   Wk, bk, K, ROWS, DMODEL, DMODEL, 1.f, 0);
    sgemm_kernel<<<gProj, 256>>>(value, Wv, bv, V, ROWS, DMODEL, DMODEL, 1.f, 0);

    // 4-5: feature projections  dash = (scale*Y512) @ feats^T   (32768 x 256 x 512)
    dim3 gFeat(MFEAT/128, ROWS2/128);
    sgemm_kernel<<<gFeat, 256>>>(Q, feats, nullptr, dQ, ROWS2, MFEAT, DEPTH, FSCALE, 1);
    sgemm_kernel<<<gFeat, 256>>>(K, feats, nullptr, dK, ROWS2, MFEAT, DEPTH, FSCALE, 1);

    // 6: q' (fused diag + rowmax + exp, in place)
    qprime_kernel<<<ROWS2/8, 256>>>(Q, dQ);

    // 7-9: k'  (diag+rowmax per row, global max per (b,h), exp)
    kstat_kernel<<<ROWS2/8, 256>>>(K, dK, diagK, rmaxK);
    kmax_kernel<<<BATCH*HEADS, 256>>>(rmaxK, kmax);
    {
        size_t total = (size_t)ROWS2 * MFEAT;
        kexp_kernel<<<(unsigned)((total + 255)/256), 256>>>(dK, diagK, kmax);
    }

    // 10: per-(s,h) 4x4 batch-mix attention, scrambled store into concat layout
    attn_mix_kernel<<<SEQ*HEADS, 256>>>(dQ, dK, V, C);

    // 11: out = C @ Wo + bo
    sgemm_kernel<<<gProj, 256>>>(C, Wo, bo, out, ROWS, DMODEL, DMODEL, 1.f, 0);
}

// round 2
// speedup vs baseline: 2.5717x; 2.5717x over previous
#include <cuda_runtime.h>
#include <cuda_bf16.h>
#include <math.h>

// ---------------------------------------------------------------------------
// Problem constants
//   B=4, L=4096, D_MODEL=1024, H=2, DEPTH=512, M_FEAT=256
// ---------------------------------------------------------------------------
#define BATCH     4
#define SEQ       4096
#define DMODEL    1024
#define HEADS     2
#define DEPTH     512
#define MFEAT     256
#define ROWS      (BATCH*SEQ)          // 16384
#define ROWS2     (ROWS*HEADS)         // 32768

#define SCALE2    0.044194173824159216f   // 1/sqrt(512)
#define FSCALE    0.21022410381342864f    // 512^{-0.25}
#define RATIO     0.0625f                 // 1/sqrt(256)
#define EPS       1e-6f

// ---------------------------------------------------------------------------
// Scratch (device globals; allocation is banned)
// ---------------------------------------------------------------------------
__device__ float g_Q [ (size_t)ROWS * DMODEL ];
__device__ float g_K [ (size_t)ROWS * DMODEL ];
__device__ float g_V [ (size_t)ROWS * DMODEL ];
__device__ float g_dQ[ (size_t)ROWS2 * MFEAT ];
__device__ float g_dK[ (size_t)ROWS2 * MFEAT ];
__device__ float g_diagK[ ROWS2 ];
__device__ float g_rmaxK[ ROWS2 ];
__device__ float g_kmax [ BATCH*HEADS ];
__device__ float g_C [ (size_t)ROWS * DMODEL ];

// ---------------------------------------------------------------------------
// TF32 helpers
// ---------------------------------------------------------------------------
__device__ __forceinline__ float to_tf32(float x) {
    float r;
    asm("cvt.rna.tf32.f32 %0, %1;" : "=f"(r) : "f"(x));
    return r;
}

__device__ __forceinline__ void mma_tf32(float c[4], const float a[4], const float b[2]) {
    asm volatile(
        "mma.sync.aligned.m16n8k8.row.col.f32.tf32.tf32.f32 "
        "{%0,%1,%2,%3}, {%4,%5,%6,%7}, {%8,%9}, {%0,%1,%2,%3};"
        : "+f"(c[0]), "+f"(c[1]), "+f"(c[2]), "+f"(c[3])
        : "r"(__float_as_uint(a[0])), "r"(__float_as_uint(a[1])),
          "r"(__float_as_uint(a[2])), "r"(__float_as_uint(a[3])),
          "r"(__float_as_uint(b[0])), "r"(__float_as_uint(b[1])));
}

// ---------------------------------------------------------------------------
// TF32 GEMM: C = alpha * A(MxK) * op(B) (+ bias)
//   bTrans==0 : B is [K,N] row-major
//   bTrans==1 : B is [N,K] row-major  (A @ B^T)
// Tiles: CTA 128x128, K-step 16, 8 warps (warp tile 64x32), double-buffered.
// Requires M%128==0, N%128==0, K%16==0.
// ---------------------------------------------------------------------------
#define AS_STRIDE 20     // 16 k + 4 pad  (floats)
#define BS_STRIDE 136    // 128 n + 8 pad (floats)

__global__ __launch_bounds__(256)
void tf32_gemm(const float* __restrict__ A, const float* __restrict__ B,
               const float* __restrict__ bias, float* __restrict__ C,
               int M, int N, int K, float alpha, int bTrans)
{
    __shared__ float As[2][128][AS_STRIDE];   // [m][k]
    __shared__ float Bs[2][16][BS_STRIDE];    // [k][n]

    const int tid  = threadIdx.x;
    const int lane = tid & 31;
    const int wid  = tid >> 5;
    const int bm   = blockIdx.y * 128;
    const int bn   = blockIdx.x * 128;

    const int warp_m = (wid & 1) * 64;   // 2 warps along m
    const int warp_n = (wid >> 1) * 32;  // 4 warps along n
    const int lr = lane >> 2;            // 0..7
    const int lc = lane & 3;             // 0..3

    // staging indices
    const int a_row = tid >> 1;              // 0..127
    const int a_kg  = (tid & 1) * 8;         // 0 or 8
    const int b_kr  = tid >> 4;              // 0..15   (bTrans==0)
    const int b_ng  = (tid & 15) * 8;        //         (bTrans==0)
    const int bt_n  = tid >> 1;              // 0..127  (bTrans==1)
    const int bt_kg = (tid & 1) * 8;         //         (bTrans==1)

    float acc[4][4][4];
    #pragma unroll
    for (int i = 0; i < 4; i++)
        #pragma unroll
        for (int j = 0; j < 4; j++)
            #pragma unroll
            for (int r = 0; r < 4; r++) acc[i][j][r] = 0.f;

    float4 pa0, pa1, pb0, pb1;

    // ---- prefetch tile 0 into registers
    {
        const float* ap = A + (size_t)(bm + a_row) * K + a_kg;
        pa0 = *reinterpret_cast<const float4*>(ap);
        pa1 = *reinterpret_cast<const float4*>(ap + 4);
        if (!bTrans) {
            const float* bp = B + (size_t)b_kr * N + bn + b_ng;
            pb0 = *reinterpret_cast<const float4*>(bp);
            pb1 = *reinterpret_cast<const float4*>(bp + 4);
        } else {
            const float* bp = B + (size_t)(bn + bt_n) * K + bt_kg;
            pb0 = *reinterpret_cast<const float4*>(bp);
            pb1 = *reinterpret_cast<const float4*>(bp + 4);
        }
    }

    // ---- store stage 0
    {
        float av[8] = {pa0.x,pa0.y,pa0.z,pa0.w,pa1.x,pa1.y,pa1.z,pa1.w};
        #pragma unroll
        for (int j = 0; j < 8; j++) As[0][a_row][a_kg + j] = to_tf32(av[j]);
        float bv[8] = {pb0.x,pb0.y,pb0.z,pb0.w,pb1.x,pb1.y,pb1.z,pb1.w};
        if (!bTrans) {
            #pragma unroll
            for (int j = 0; j < 8; j++) Bs[0][b_kr][b_ng + j] = to_tf32(bv[j]);
        } else {
            #pragma unroll
            for (int j = 0; j < 8; j++) Bs[0][bt_kg + j][bt_n] = to_tf32(bv[j]);
        }
    }
    __syncthreads();

    const int nstages = K >> 4;
    for (int s = 0; s < nstages; s++) {
        const int buf = s & 1;
        const int kb_next = (s + 1) << 4;

        // prefetch next tile
        if (s + 1 < nstages) {
            const float* ap = A + (size_t)(bm + a_row) * K + kb_next + a_kg;
            pa0 = *reinterpret_cast<const float4*>(ap);
            pa1 = *reinterpret_cast<const float4*>(ap + 4);
            if (!bTrans) {
                const float* bp = B + (size_t)(kb_next + b_kr) * N + bn + b_ng;
                pb0 = *reinterpret_cast<const float4*>(bp);
                pb1 = *reinterpret_cast<const float4*>(bp + 4);
            } else {
                const float* bp = B + (size_t)(bn + bt_n) * K + kb_next + bt_kg;
                pb0 = *reinterpret_cast<const float4*>(bp);
                pb1 = *reinterpret_cast<const float4*>(bp + 4);
            }
        }

        // compute on buf
        #pragma unroll
        for (int kk = 0; kk < 16; kk += 8) {
            float a[4][4], b[4][2];
            #pragma unroll
            for (int mi = 0; mi < 4; mi++) {
                int m = warp_m + mi * 16 + lr;
                a[mi][0] = As[buf][m    ][kk + lc];
                a[mi][1] = As[buf][m + 8][kk + lc];
                a[mi][2] = As[buf][m    ][kk + lc + 4];
                a[mi][3] = As[buf][m + 8][kk + lc + 4];
            }
            #pragma unroll
            for (int ni = 0; ni < 4; ni++) {
                int n = warp_n + ni * 8 + lr;
                b[ni][0] = Bs[buf][kk + lc    ][n];
                b[ni][1] = Bs[buf][kk + lc + 4][n];
            }
            #pragma unroll
            for (int mi = 0; mi < 4; mi++)
                #pragma unroll
                for (int ni = 0; ni < 4; ni++)
                    mma_tf32(acc[mi][ni], a[mi], b[ni]);
        }

        // store next stage
        if (s + 1 < nstages) {
            const int nb = buf ^ 1;
            float av[8] = {pa0.x,pa0.y,pa0.z,pa0.w,pa1.x,pa1.y,pa1.z,pa1.w};
            #pragma unroll
            for (int j = 0; j < 8; j++) As[nb][a_row][a_kg + j] = to_tf32(av[j]);
            float bv[8] = {pb0.x,pb0.y,pb0.z,pb0.w,pb1.x,pb1.y,pb1.z,pb1.w};
            if (!bTrans) {
                #pragma unroll
                for (int j = 0; j < 8; j++) Bs[nb][b_kr][b_ng + j] = to_tf32(bv[j]);
            } else {
                #pragma unroll
                for (int j = 0; j < 8; j++) Bs[nb][bt_kg + j][bt_n] = to_tf32(bv[j]);
            }
        }
        __syncthreads();
    }

    // ---- epilogue: c0,c1 at (row, 2*lc), c2,c3 at (row+8, 2*lc)
    #pragma unroll
    for (int mi = 0; mi < 4; mi++) {
        #pragma unroll
        for (int ni = 0; ni < 4; ni++) {
            int row = bm + warp_m + mi * 16 + lr;
            int col = bn + warp_n + ni * 8 + 2 * lc;
            float b0 = bias ? bias[col]     : 0.f;
            float b1 = bias ? bias[col + 1] : 0.f;
            float2 v0 = make_float2(alpha * acc[mi][ni][0] + b0,
                                    alpha * acc[mi][ni][1] + b1);
            float2 v1 = make_float2(alpha * acc[mi][ni][2] + b0,
                                    alpha * acc[mi][ni][3] + b1);
            *reinterpret_cast<float2*>(&C[(size_t)row * N + col])       = v0;
            *reinterpret_cast<float2*>(&C[(size_t)(row + 8) * N + col]) = v1;
        }
    }
}

// ---------------------------------------------------------------------------
// q' : per row (32768) diag from Y row, row-max of dash row, exp (in place)
// one warp per row
// ---------------------------------------------------------------------------
__global__ __launch_bounds__(256)
void qprime_kernel(const float* __restrict__ Y, float* __restrict__ dash)
{
    int warp = (blockIdx.x * blockDim.x + threadIdx.x) >> 5;
    int lane = threadIdx.x & 31;
    if (warp >= ROWS2) return;

    const float* y = Y + (size_t)warp * DEPTH;
    float ss = 0.f;
    #pragma unroll
    for (int i = 0; i < DEPTH/32; i++) { float v = y[lane + 32*i]; ss += v*v; }
    #pragma unroll
    for (int off = 16; off; off >>= 1) ss += __shfl_xor_sync(0xffffffff, ss, off);
    float diag = 0.5f * SCALE2 * ss;

    float* dr = dash + (size_t)warp * MFEAT;
    float vals[MFEAT/32];
    float mx = -1e30f;
    #pragma unroll
    for (int i = 0; i < MFEAT/32; i++) { vals[i] = dr[lane + 32*i]; mx = fmaxf(mx, vals[i]); }
    #pragma unroll
    for (int off = 16; off; off >>= 1) mx = fmaxf(mx, __shfl_xor_sync(0xffffffff, mx, off));

    #pragma unroll
    for (int i = 0; i < MFEAT/32; i++)
        dr[lane + 32*i] = RATIO * (expf(vals[i] - diag - mx) + EPS);
}

// ---------------------------------------------------------------------------
// k path step 1: per-row diag + per-row max
// ---------------------------------------------------------------------------
__global__ __launch_bounds__(256)
void kstat_kernel(const float* __restrict__ Y, const float* __restrict__ dash,
                  float* __restrict__ diagK, float* __restrict__ rmaxK)
{
    int warp = (blockIdx.x * blockDim.x + threadIdx.x) >> 5;
    int lane = threadIdx.x & 31;
    if (warp >= ROWS2) return;

    const float* y = Y + (size_t)warp * DEPTH;
    float ss = 0.f;
    #pragma unroll
    for (int i = 0; i < DEPTH/32; i++) { float v = y[lane + 32*i]; ss += v*v; }
    #pragma unroll
    for (int off = 16; off; off >>= 1) ss += __shfl_xor_sync(0xffffffff, ss, off);

    const float* dr = dash + (size_t)warp * MFEAT;
    float mx = -1e30f;
    #pragma unroll
    for (int i = 0; i < MFEAT/32; i++) mx = fmaxf(mx, dr[lane + 32*i]);
    #pragma unroll
    for (int off = 16; off; off >>= 1) mx = fmaxf(mx, __shfl_xor_sync(0xffffffff, mx, off));

    if (lane == 0) { diagK[warp] = 0.5f * SCALE2 * ss; rmaxK[warp] = mx; }
}

// k path step 2: reduce row maxima over the sequence per (b,h)
__global__ __launch_bounds__(256)
void kmax_kernel(const float* __restrict__ rmaxK, float* __restrict__ kmax)
{
    int bh = blockIdx.x;
    int b  = bh >> 1, h = bh & 1;
    __shared__ float sm[256];
    float mx = -1e30f;
    for (int l = threadIdx.x; l < SEQ; l += 256)
        mx = fmaxf(mx, rmaxK[b*8192 + l*2 + h]);
    sm[threadIdx.x] = mx;
    __syncthreads();
    for (int s = 128; s; s >>= 1) {
        if (threadIdx.x < s) sm[threadIdx.x] = fmaxf(sm[threadIdx.x], sm[threadIdx.x + s]);
        __syncthreads();
    }
    if (threadIdx.x == 0) kmax[bh] = sm[0];
}

// k path step 3
__global__ __launch_bounds__(256)
void kexp_kernel(float* __restrict__ dash, const float* __restrict__ diagK,
                 const float* __restrict__ kmax)
{
    size_t idx = (size_t)blockIdx.x * blockDim.x + threadIdx.x;
    size_t total = (size_t)ROWS2 * MFEAT;
    if (idx >= total) return;
    int r = (int)(idx >> 8);
    int b = r >> 13;
    int h = r & 1;
    float v = dash[idx];
    dash[idx] = RATIO * (expf(v - diagK[r] - kmax[b*2 + h]) + EPS);
}

// ---------------------------------------------------------------------------
// Attention mix: per (s,h) block; 4x4 batch mix, scrambled concat store
// ---------------------------------------------------------------------------
__global__ __launch_bounds__(256)
void attn_mix_kernel(const float* __restrict__ QP, const float* __restrict__ KP,
                     const float* __restrict__ V, float* __restrict__ C)
{
    int blk = blockIdx.x;
    int s = blk >> 1, h = blk & 1;
    __shared__ float q_s[4][MFEAT];
    __shared__ float k_s[4][MFEAT];
    __shared__ float S[4][4];
    __shared__ float rs[4];
    int tid = threadIdx.x;

    #pragma unroll
    for (int bb = 0; bb < 4; bb++) {
        size_t r = (size_t)((bb*SEQ + s)*HEADS + h);
        q_s[bb][tid] = QP[r*MFEAT + tid];
        k_s[bb][tid] = KP[r*MFEAT + tid];
    }
    __syncthreads();

    int p = tid >> 4, lane16 = tid & 15;
    int bb = p >> 2, bp = p & 3;
    float acc = 0.f;
    #pragma unroll
    for (int m = 0; m < MFEAT; m += 16) acc += q_s[bb][m + lane16] * k_s[bp][m + lane16];
    #pragma unroll
    for (int off = 8; off; off >>= 1) acc += __shfl_down_sync(0xffffffff, acc, off, 16);
    if (lane16 == 0) S[bb][bp] = acc;
    __syncthreads();
    if (tid < 4) rs[tid] = S[tid][0] + S[tid][1] + S[tid][2] + S[tid][3];
    __syncthreads();

    float s00=S[0][0],s01=S[0][1],s02=S[0][2],s03=S[0][3];
    float s10=S[1][0],s11=S[1][1],s12=S[1][2],s13=S[1][3];
    float s20=S[2][0],s21=S[2][1],s22=S[2][2],s23=S[2][3];
    float s30=S[3][0],s31=S[3][1],s32=S[3][2],s33=S[3][3];
    float r0 = 1.f/rs[0], r1 = 1.f/rs[1], r2 = 1.f/rs[2], r3 = 1.f/rs[3];

    size_t cbase = (size_t)s*4096 + (size_t)h*2048;
    for (int d = tid; d < DEPTH; d += 256) {
        float v0 = V[(size_t)((0*SEQ + s)*HEADS + h)*DEPTH + d];
        float v1 = V[(size_t)((1*SEQ + s)*HEADS + h)*DEPTH + d];
        float v2 = V[(size_t)((2*SEQ + s)*HEADS + h)*DEPTH + d];
        float v3 = V[(size_t)((3*SEQ + s)*HEADS + h)*DEPTH + d];
        C[cbase + 0*512 + d] = (s00*v0 + s01*v1 + s02*v2 + s03*v3) * r0;
        C[cbase + 1*512 + d] = (s10*v0 + s11*v1 + s12*v2 + s13*v3) * r1;
        C[cbase + 2*512 + d] = (s20*v0 + s21*v1 + s22*v2 + s23*v3) * r2;
        C[cbase + 3*512 + d] = (s30*v0 + s31*v1 + s32*v2 + s33*v3) * r3;
    }
}

// ---------------------------------------------------------------------------
// Launch
// ---------------------------------------------------------------------------
extern "C" void kernel_launch(void* const* d_in, const int* in_sizes, int n_in,
                              void* d_out, int out_size)
{
    const float* query = (const float*)d_in[0];
    const float* key   = (const float*)d_in[1];
    const float* value = (const float*)d_in[2];
    const float* Wq = (const float*)d_in[4];
    const float* bq = (const float*)d_in[5];
    const float* Wk = (const float*)d_in[6];
    const float* bk = (const float*)d_in[7];
    const float* Wv = (const float*)d_in[8];
    const float* bv = (const float*)d_in[9];
    const float* Wo = (const float*)d_in[10];
    const float* bo = (const float*)d_in[11];
    const float* feats = (const float*)d_in[12];   // [256, 512]
    float* out = (float*)d_out;

    float *Q, *K, *V, *dQ, *dK, *diagK, *rmaxK, *kmax, *C;
    cudaGetSymbolAddress((void**)&Q,     g_Q);
    cudaGetSymbolAddress((void**)&K,     g_K);
    cudaGetSymbolAddress((void**)&V,     g_V);
    cudaGetSymbolAddress((void**)&dQ,    g_dQ);
    cudaGetSymbolAddress((void**)&dK,    g_dK);
    cudaGetSymbolAddress((void**)&diagK, g_diagK);
    cudaGetSymbolAddress((void**)&rmaxK, g_rmaxK);
    cudaGetSymbolAddress((void**)&kmax,  g_kmax);
    cudaGetSymbolAddress((void**)&C,     g_C);

    // 1-3: projections  Y = X @ W + b     (16384 x 1024 x 1024)
    dim3 gProj(DMODEL/128, ROWS/128);
    tf32_gemm<<<gProj, 256>>>(query, Wq, bq, Q, ROWS, DMODEL, DMODEL, 1.f, 0);
    tf32_gemm<<<gProj, 256>>>(key,   Wk, bk, K, ROWS, DMODEL, DMODEL, 1.f, 0);
    tf32_gemm<<<gProj, 256>>>(value, Wv, bv, V, ROWS, DMODEL, DMODEL, 1.f, 0);

    // 4-5: feature projections  dash = (scale*Y512) @ feats^T   (32768 x 256 x 512)
    dim3 gFeat(MFEAT/128, ROWS2/128);
    tf32_gemm<<<gFeat, 256>>>(Q, feats, nullptr, dQ, ROWS2, MFEAT, DEPTH, FSCALE, 1);
    tf32_gemm<<<gFeat, 256>>>(K, feats, nullptr, dK, ROWS2, MFEAT, DEPTH, FSCALE, 1);

    // 6: q'
    qprime_kernel<<<ROWS2/8, 256>>>(Q, dQ);

    // 7-9: k'
    kstat_kernel<<<ROWS2/8, 256>>>(K, dK, diagK, rmaxK);
    kmax_kernel<<<BATCH*HEADS, 256>>>(rmaxK, kmax);
    {
        size_t total = (size_t)ROWS2 * MFEAT;
        kexp_kernel<<<(unsigned)((total + 255)/256), 256>>>(dK, diagK, kmax);
    }

    // 10: attention mix
    attn_mix_kernel<<<SEQ*HEADS, 256>>>(dQ, dK, V, C);

    // 11: out = C @ Wo + bo
    tf32_gemm<<<gProj, 256>>>(C, Wo, bo, out, ROWS, DMODEL, DMODEL, 1.f, 0);
}